// round 1
// baseline (speedup 1.0000x reference)
#include <cuda_runtime.h>

#define T_TOKENS 16384
#define H_DIM    2880
#define E_EXP    32
#define TOPK     4
#define BM       128
#define BK       32
#define NTHREADS 256
#define NTILES   (H_DIM / BK)   // 90

typedef unsigned long long u64;

__device__ __forceinline__ u64 ffma2(u64 a, u64 b, u64 c) {
    u64 d;
    asm("fma.rn.f32x2 %0, %1, %2, %3;" : "=l"(d) : "l"(a), "l"(b), "l"(c));
    return d;
}
__device__ __forceinline__ u64 pack2(float x) {
    u64 d;
    asm("mov.b64 %0, {%1, %1};" : "=l"(d) : "f"(x));
    return d;
}
__device__ __forceinline__ void unpack2(u64 v, float& lo, float& hi) {
    asm("mov.b64 {%0, %1}, %2;" : "=f"(lo), "=f"(hi) : "l"(v));
}

__global__ __launch_bounds__(NTHREADS)
void gate_kernel(const float* __restrict__ x,
                 const float* __restrict__ w,
                 const float* __restrict__ bias,
                 float* __restrict__ out)
{
    __shared__ __align__(16) float xs[BK][BM + 4];      // transposed x tile, stride 132 (16B aligned rows)
    __shared__ __align__(16) float ws[BK][E_EXP + 1];   // transposed w tile, pad 33 -> conflict-free STS
    __shared__ __align__(16) float logits[BM][E_EXP + 1];
    __shared__ float bias_s[E_EXP];

    const int tid = threadIdx.x;
    const int t0  = blockIdx.x * BM;

    if (tid < E_EXP) bias_s[tid] = bias[tid];

    const int r = tid >> 3;   // token group: tokens r*4 .. r*4+3
    const int c = tid & 7;    // expert group: experts c*4 .. c*4+3

    // accumulators: acc[p][j] = f32x2 of tokens (r*4+2p, r*4+2p+1) for expert c*4+j
    u64 acc[2][4];
    #pragma unroll
    for (int p = 0; p < 2; ++p)
        #pragma unroll
        for (int j = 0; j < 4; ++j) acc[p][j] = 0ull;

    // gmem load mapping (per k-tile):
    //  x: idx = tid + 256*i (i<4): tok = idx>>3, jj = idx&7 -> float4 at x[(t0+tok)*H + k0 + 4*jj]
    //  w: e = tid>>3, jj = tid&7 -> float4 at w[e*H + k0 + 4*jj]
    float4 xr[4];
    float4 wr;

    // prologue: prefetch tile 0
    {
        const int k0 = 0;
        #pragma unroll
        for (int i = 0; i < 4; ++i) {
            int idx = tid + NTHREADS * i;
            int tok = idx >> 3, jj = idx & 7;
            xr[i] = *reinterpret_cast<const float4*>(&x[(size_t)(t0 + tok) * H_DIM + k0 + 4 * jj]);
        }
        wr = *reinterpret_cast<const float4*>(&w[(size_t)(tid >> 3) * H_DIM + k0 + 4 * (tid & 7)]);
    }

    for (int kt = 0; kt < NTILES; ++kt) {
        __syncthreads();   // previous compute done before smem overwrite (no-op cost on first iter)

        // store prefetched tile to smem (transposed)
        #pragma unroll
        for (int i = 0; i < 4; ++i) {
            int idx = tid + NTHREADS * i;
            int tok = idx >> 3, jj = idx & 7;
            xs[4 * jj + 0][tok] = xr[i].x;
            xs[4 * jj + 1][tok] = xr[i].y;
            xs[4 * jj + 2][tok] = xr[i].z;
            xs[4 * jj + 3][tok] = xr[i].w;
        }
        {
            int e = tid >> 3, jj = tid & 7;
            ws[4 * jj + 0][e] = wr.x;
            ws[4 * jj + 1][e] = wr.y;
            ws[4 * jj + 2][e] = wr.z;
            ws[4 * jj + 3][e] = wr.w;
        }
        __syncthreads();

        // prefetch next tile (overlaps with compute via ILP)
        if (kt + 1 < NTILES) {
            const int k0 = (kt + 1) * BK;
            #pragma unroll
            for (int i = 0; i < 4; ++i) {
                int idx = tid + NTHREADS * i;
                int tok = idx >> 3, jj = idx & 7;
                xr[i] = *reinterpret_cast<const float4*>(&x[(size_t)(t0 + tok) * H_DIM + k0 + 4 * jj]);
            }
            wr = *reinterpret_cast<const float4*>(&w[(size_t)(tid >> 3) * H_DIM + k0 + 4 * (tid & 7)]);
        }

        // compute: 32 k-steps
        #pragma unroll
        for (int kk = 0; kk < BK; ++kk) {
            const ulonglong2 aa = *reinterpret_cast<const ulonglong2*>(&xs[kk][r * 4]);
            u64 b0 = pack2(ws[kk][c * 4 + 0]);
            u64 b1 = pack2(ws[kk][c * 4 + 1]);
            u64 b2 = pack2(ws[kk][c * 4 + 2]);
            u64 b3 = pack2(ws[kk][c * 4 + 3]);
            acc[0][0] = ffma2(aa.x, b0, acc[0][0]);
            acc[0][1] = ffma2(aa.x, b1, acc[0][1]);
            acc[0][2] = ffma2(aa.x, b2, acc[0][2]);
            acc[0][3] = ffma2(aa.x, b3, acc[0][3]);
            acc[1][0] = ffma2(aa.y, b0, acc[1][0]);
            acc[1][1] = ffma2(aa.y, b1, acc[1][1]);
            acc[1][2] = ffma2(aa.y, b2, acc[1][2]);
            acc[1][3] = ffma2(aa.y, b3, acc[1][3]);
        }
    }

    __syncthreads();
    // write accumulators to logits smem
    #pragma unroll
    for (int p = 0; p < 2; ++p) {
        #pragma unroll
        for (int j = 0; j < 4; ++j) {
            float lo, hi;
            unpack2(acc[p][j], lo, hi);
            logits[r * 4 + 2 * p + 0][c * 4 + j] = lo;
            logits[r * 4 + 2 * p + 1][c * 4 + j] = hi;
        }
    }
    __syncthreads();

    // epilogue: top-4 + softmax, one thread per token (threads 0..127)
    if (tid < BM) {
        const int t = tid;
        float bv0 = -1e30f, bv1 = -1e30f, bv2 = -1e30f, bv3 = -1e30f;
        int   bi0 = 0, bi1 = 0, bi2 = 0, bi3 = 0;
        #pragma unroll
        for (int e = 0; e < E_EXP; ++e) {
            float lv = logits[t][e] + bias_s[e];
            if (lv > bv3) {
                if (lv > bv0) {
                    bv3 = bv2; bi3 = bi2; bv2 = bv1; bi2 = bi1; bv1 = bv0; bi1 = bi0;
                    bv0 = lv;  bi0 = e;
                } else if (lv > bv1) {
                    bv3 = bv2; bi3 = bi2; bv2 = bv1; bi2 = bi1;
                    bv1 = lv;  bi1 = e;
                } else if (lv > bv2) {
                    bv3 = bv2; bi3 = bi2;
                    bv2 = lv;  bi2 = e;
                } else {
                    bv3 = lv;  bi3 = e;
                }
            }
        }
        // softmax over the 4 selected logits (bv0 is the max)
        float e0 = expf(bv0 - bv0);
        float e1 = expf(bv1 - bv0);
        float e2 = expf(bv2 - bv0);
        float e3 = expf(bv3 - bv0);
        float inv = 1.0f / (e0 + e1 + e2 + e3);

        const int gt = t0 + t;
        // output layout: [T*K] topk indices (as float), then [T*K] topk weights
        float* oi = out + (size_t)gt * TOPK;
        float* ow = out + (size_t)T_TOKENS * TOPK + (size_t)gt * TOPK;
        oi[0] = (float)bi0; oi[1] = (float)bi1; oi[2] = (float)bi2; oi[3] = (float)bi3;
        ow[0] = e0 * inv;   ow[1] = e1 * inv;   ow[2] = e2 * inv;   ow[3] = e3 * inv;
    }
}

extern "C" void kernel_launch(void* const* d_in, const int* in_sizes, int n_in,
                              void* d_out, int out_size)
{
    const float* x    = (const float*)d_in[0];  // hidden_states [4,4096,2880] f32
    const float* w    = (const float*)d_in[1];  // weight [32,2880] f32
    const float* bias = (const float*)d_in[2];  // bias [32] f32
    float* out = (float*)d_out;

    dim3 grid(T_TOKENS / BM);   // 128 blocks
    dim3 block(NTHREADS);
    gate_kernel<<<grid, block>>>(x, w, bias, out);
}

// round 2
// speedup vs baseline: 1.1938x; 1.1938x over previous
#include <cuda_runtime.h>

#define T_TOKENS 16384
#define H_DIM    2880
#define E_EXP    32
#define TOPK     4
#define BM       32
#define BK       32
#define NTILES   (H_DIM / BK)   // 90
#define NTHREADS 128
#define XSTRIDE  36             // floats per row (pad 32->36: rows shift 4 banks)

typedef unsigned long long u64;

__device__ __forceinline__ u64 ffma2(u64 a, u64 b, u64 c) {
    u64 d;
    asm("fma.rn.f32x2 %0, %1, %2, %3;" : "=l"(d) : "l"(a), "l"(b), "l"(c));
    return d;
}
__device__ __forceinline__ unsigned smem_u32(const void* p) {
    return (unsigned)__cvta_generic_to_shared(p);
}
__device__ __forceinline__ void cp16(unsigned dst, const void* src) {
    asm volatile("cp.async.cg.shared.global [%0], [%1], 16;" :: "r"(dst), "l"(src));
}
__device__ __forceinline__ void cp_commit() {
    asm volatile("cp.async.commit_group;");
}
template <int N>
__device__ __forceinline__ void cp_wait() {
    asm volatile("cp.async.wait_group %0;" :: "n"(N));
}
__device__ __forceinline__ float hadd2(u64 v) {
    float lo, hi;
    asm("mov.b64 {%0, %1}, %2;" : "=f"(lo), "=f"(hi) : "l"(v));
    return lo + hi;
}

__global__ __launch_bounds__(NTHREADS)
void gate_kernel(const float* __restrict__ x,
                 const float* __restrict__ w,
                 const float* __restrict__ bias,
                 float* __restrict__ out)
{
    // K-major tiles, double buffered. No transpose needed (f32x2 paired along K).
    __shared__ __align__(16) float xs[2][BM][XSTRIDE];      // 2*32*36*4 = 9216 B
    __shared__ __align__(16) float ws[2][E_EXP][XSTRIDE];   // 9216 B
    __shared__ float bias_s[E_EXP];

    const int tid = threadIdx.x;
    const int t0  = blockIdx.x * BM;

    if (tid < E_EXP) bias_s[tid] = bias[tid];

    // compute mapping: tokens {r, r+16}, experts {c, c+8, c+16, c+24}
    const int r = tid >> 3;       // 0..15
    const int c = tid & 7;        // 0..7

    // cp.async mapping: each tile = 32 rows x 8 chunks(16B) = 256 chunks for x and for w.
    // thread copies chunks tid and tid+128 of each: row = chunk>>3 (0..31), col = chunk&7.
    const int crow = tid >> 3;        // 0..15
    const int ccol = tid & 7;         // 0..7
    const float* xsrc0 = x + (size_t)(t0 + crow)      * H_DIM + ccol * 4;
    const float* xsrc1 = x + (size_t)(t0 + crow + 16) * H_DIM + ccol * 4;
    const float* wsrc0 = w + (size_t)(crow)      * H_DIM + ccol * 4;
    const float* wsrc1 = w + (size_t)(crow + 16) * H_DIM + ccol * 4;

    unsigned xd[2][2], wd[2][2];
    #pragma unroll
    for (int b = 0; b < 2; ++b) {
        xd[b][0] = smem_u32(&xs[b][crow][ccol * 4]);
        xd[b][1] = smem_u32(&xs[b][crow + 16][ccol * 4]);
        wd[b][0] = smem_u32(&ws[b][crow][ccol * 4]);
        wd[b][1] = smem_u32(&ws[b][crow + 16][ccol * 4]);
    }

    // accumulators: acc[i][j] = f32x2 partial sums over paired k, token (r+16i), expert (c+8j)
    u64 acc[2][4];
    #pragma unroll
    for (int i = 0; i < 2; ++i)
        #pragma unroll
        for (int j = 0; j < 4; ++j) acc[i][j] = 0ull;

    // prologue: tile 0 -> buffer 0
    cp16(xd[0][0], xsrc0);
    cp16(xd[0][1], xsrc1);
    cp16(wd[0][0], wsrc0);
    cp16(wd[0][1], wsrc1);
    cp_commit();

    for (int kt = 0; kt < NTILES; ++kt) {
        if (kt + 1 < NTILES) {
            const int nb = (kt + 1) & 1;
            const size_t koff = (size_t)(kt + 1) * BK;
            cp16(xd[nb][0], xsrc0 + koff);
            cp16(xd[nb][1], xsrc1 + koff);
            cp16(wd[nb][0], wsrc0 + koff);
            cp16(wd[nb][1], wsrc1 + koff);
            cp_commit();
            cp_wait<1>();   // tile kt complete (this thread)
        } else {
            cp_wait<0>();
        }
        __syncthreads();    // all threads' tile kt complete

        const float (*xb)[XSTRIDE] = xs[kt & 1];
        const float (*wb)[XSTRIDE] = ws[kt & 1];

        // 8 quad-chunks of 4 k-values (2 f32x2 pairs) each
        #pragma unroll
        for (int kq = 0; kq < 8; ++kq) {
            const ulonglong2 a0 = *reinterpret_cast<const ulonglong2*>(&xb[r][kq * 4]);
            const ulonglong2 a1 = *reinterpret_cast<const ulonglong2*>(&xb[r + 16][kq * 4]);
            const ulonglong2 b0 = *reinterpret_cast<const ulonglong2*>(&wb[c][kq * 4]);
            const ulonglong2 b1 = *reinterpret_cast<const ulonglong2*>(&wb[c + 8][kq * 4]);
            const ulonglong2 b2 = *reinterpret_cast<const ulonglong2*>(&wb[c + 16][kq * 4]);
            const ulonglong2 b3 = *reinterpret_cast<const ulonglong2*>(&wb[c + 24][kq * 4]);

            acc[0][0] = ffma2(a0.x, b0.x, acc[0][0]);
            acc[0][1] = ffma2(a0.x, b1.x, acc[0][1]);
            acc[0][2] = ffma2(a0.x, b2.x, acc[0][2]);
            acc[0][3] = ffma2(a0.x, b3.x, acc[0][3]);
            acc[1][0] = ffma2(a1.x, b0.x, acc[1][0]);
            acc[1][1] = ffma2(a1.x, b1.x, acc[1][1]);
            acc[1][2] = ffma2(a1.x, b2.x, acc[1][2]);
            acc[1][3] = ffma2(a1.x, b3.x, acc[1][3]);
            acc[0][0] = ffma2(a0.y, b0.y, acc[0][0]);
            acc[0][1] = ffma2(a0.y, b1.y, acc[0][1]);
            acc[0][2] = ffma2(a0.y, b2.y, acc[0][2]);
            acc[0][3] = ffma2(a0.y, b3.y, acc[0][3]);
            acc[1][0] = ffma2(a1.y, b0.y, acc[1][0]);
            acc[1][1] = ffma2(a1.y, b1.y, acc[1][1]);
            acc[1][2] = ffma2(a1.y, b2.y, acc[1][2]);
            acc[1][3] = ffma2(a1.y, b3.y, acc[1][3]);
        }
        __syncthreads();    // compute done before next prefetch overwrites other buffer
    }

    // logits in smem (alias over xs[0], which is no longer needed): [32][33]
    float (*logits)[33] = reinterpret_cast<float (*)[33]>(&xs[0][0][0]);
    #pragma unroll
    for (int i = 0; i < 2; ++i)
        #pragma unroll
        for (int j = 0; j < 4; ++j)
            logits[r + 16 * i][c + 8 * j] = hadd2(acc[i][j]);
    __syncthreads();

    // epilogue: top-4 + softmax, one thread per token
    if (tid < BM) {
        const int t = tid;
        float bv0 = -1e30f, bv1 = -1e30f, bv2 = -1e30f, bv3 = -1e30f;
        int   bi0 = 0, bi1 = 0, bi2 = 0, bi3 = 0;
        #pragma unroll
        for (int e = 0; e < E_EXP; ++e) {
            float lv = logits[t][e] + bias_s[e];
            if (lv > bv3) {
                if (lv > bv0) {
                    bv3 = bv2; bi3 = bi2; bv2 = bv1; bi2 = bi1; bv1 = bv0; bi1 = bi0;
                    bv0 = lv;  bi0 = e;
                } else if (lv > bv1) {
                    bv3 = bv2; bi3 = bi2; bv2 = bv1; bi2 = bi1;
                    bv1 = lv;  bi1 = e;
                } else if (lv > bv2) {
                    bv3 = bv2; bi3 = bi2;
                    bv2 = lv;  bi2 = e;
                } else {
                    bv3 = lv;  bi3 = e;
                }
            }
        }
        float e0 = 1.0f;
        float e1 = expf(bv1 - bv0);
        float e2 = expf(bv2 - bv0);
        float e3 = expf(bv3 - bv0);
        float inv = 1.0f / (e0 + e1 + e2 + e3);

        const int gt = t0 + t;
        float* oi = out + (size_t)gt * TOPK;
        float* ow = out + (size_t)T_TOKENS * TOPK + (size_t)gt * TOPK;
        oi[0] = (float)bi0; oi[1] = (float)bi1; oi[2] = (float)bi2; oi[3] = (float)bi3;
        ow[0] = e0 * inv;   ow[1] = e1 * inv;   ow[2] = e2 * inv;   ow[3] = e3 * inv;
    }
}

extern "C" void kernel_launch(void* const* d_in, const int* in_sizes, int n_in,
                              void* d_out, int out_size)
{
    const float* x    = (const float*)d_in[0];  // [4,4096,2880] f32
    const float* w    = (const float*)d_in[1];  // [32,2880] f32
    const float* bias = (const float*)d_in[2];  // [32] f32
    float* out = (float*)d_out;

    dim3 grid(T_TOKENS / BM);   // 512 blocks
    dim3 block(NTHREADS);
    gate_kernel<<<grid, block>>>(x, w, bias, out);
}

// round 3
// speedup vs baseline: 1.3114x; 1.0985x over previous
#include <cuda_runtime.h>

#define T_TOKENS 16384
#define H_DIM    2880
#define E_EXP    32
#define TOPK     4
#define BM       64
#define BK       32
#define NTILES   (H_DIM / BK)   // 90
#define NTHREADS 64
#define XS       36             // smem row stride in floats (144B: conflict-free dist mod 128)

typedef unsigned long long u64;

__device__ __forceinline__ u64 ffma2(u64 a, u64 b, u64 c) {
    u64 d;
    asm("fma.rn.f32x2 %0, %1, %2, %3;" : "=l"(d) : "l"(a), "l"(b), "l"(c));
    return d;
}
__device__ __forceinline__ unsigned smem_u32(const void* p) {
    return (unsigned)__cvta_generic_to_shared(p);
}
__device__ __forceinline__ void cp16(unsigned dst, const void* src) {
    asm volatile("cp.async.cg.shared.global [%0], [%1], 16;" :: "r"(dst), "l"(src));
}
__device__ __forceinline__ void cp_commit() {
    asm volatile("cp.async.commit_group;");
}
template <int N>
__device__ __forceinline__ void cp_wait() {
    asm volatile("cp.async.wait_group %0;" :: "n"(N));
}
__device__ __forceinline__ float hadd2(u64 v) {
    float lo, hi;
    asm("mov.b64 {%0, %1}, %2;" : "=f"(lo), "=f"(hi) : "l"(v));
    return lo + hi;
}

__global__ __launch_bounds__(NTHREADS, 6)
void gate_kernel(const float* __restrict__ x,
                 const float* __restrict__ w,
                 const float* __restrict__ bias,
                 float* __restrict__ out)
{
    // triple-buffered K-major tiles (f32x2 paired along K -> no transpose, no pack)
    __shared__ __align__(16) float xs[3][BM][XS];      // 3*64*36*4 = 27648 B
    __shared__ __align__(16) float ws[3][E_EXP][XS];   // 3*32*36*4 = 13824 B
    __shared__ float bias_s[E_EXP];

    const int tid = threadIdx.x;
    const int t0  = blockIdx.x * BM;

    if (tid < E_EXP) bias_s[tid] = bias[tid];

    const int lane = tid & 31;
    const int warp = tid >> 5;
    const int r    = lane >> 3;   // 0..3  -> tokens wtok + r + 4i (i<8)
    const int c    = lane & 7;    // 0..7  -> experts c + 8j (j<4)
    const int wtok = warp * 32;

    // cp.async mapping: chunk = tid + 64*i -> row = (tid>>3) + 8*i, col16B = tid&7
    const int prow = tid >> 3;    // 0..7
    const int pcol = tid & 7;     // 0..7
    const float* xsrc = x + (size_t)(t0 + prow) * H_DIM + pcol * 4;
    const float* wsrc = w + (size_t)prow * H_DIM + pcol * 4;

    // acc[i][j]: f32x2 partials (paired k) for token wtok+r+4i, expert c+8j
    u64 acc[8][4];
    #pragma unroll
    for (int i = 0; i < 8; ++i)
        #pragma unroll
        for (int j = 0; j < 4; ++j) acc[i][j] = 0ull;

    auto prefetch = [&](int kt, int buf) {
        const size_t k0 = (size_t)kt * BK;
        #pragma unroll
        for (int i = 0; i < 8; ++i)
            cp16(smem_u32(&xs[buf][prow + 8 * i][pcol * 4]),
                 xsrc + k0 + (size_t)(8 * i) * H_DIM);
        #pragma unroll
        for (int i = 0; i < 4; ++i)
            cp16(smem_u32(&ws[buf][prow + 8 * i][pcol * 4]),
                 wsrc + k0 + (size_t)(8 * i) * H_DIM);
        cp_commit();
    };

    // prologue: stage tiles 0 and 1
    prefetch(0, 0);
    prefetch(1, 1);

    int buf = 0;
    for (int kt = 0; kt < NTILES; ++kt) {
        if (kt + 2 < NTILES) {
            prefetch(kt + 2, (kt + 2) % 3);
            cp_wait<2>();          // tile kt's group complete
        } else if (kt + 1 < NTILES) {
            cp_wait<1>();
        } else {
            cp_wait<0>();
        }
        __syncthreads();

        const float (*xb)[XS] = xs[buf];
        const float (*wb)[XS] = ws[buf];

        #pragma unroll 2
        for (int kq = 0; kq < 8; ++kq) {
            ulonglong2 a[8], b[4];
            #pragma unroll
            for (int i = 0; i < 8; ++i)
                a[i] = *reinterpret_cast<const ulonglong2*>(&xb[wtok + r + 4 * i][kq * 4]);
            #pragma unroll
            for (int j = 0; j < 4; ++j)
                b[j] = *reinterpret_cast<const ulonglong2*>(&wb[c + 8 * j][kq * 4]);

            #pragma unroll
            for (int i = 0; i < 8; ++i)
                #pragma unroll
                for (int j = 0; j < 4; ++j)
                    acc[i][j] = ffma2(a[i].x, b[j].x, acc[i][j]);
            #pragma unroll
            for (int i = 0; i < 8; ++i)
                #pragma unroll
                for (int j = 0; j < 4; ++j)
                    acc[i][j] = ffma2(a[i].y, b[j].y, acc[i][j]);
        }
        __syncthreads();           // compute done before buf is overwritten next iter
        buf = (buf == 2) ? 0 : buf + 1;
    }

    // logits in smem (alias over xs, no longer needed): [64][33]
    float (*logits)[33] = reinterpret_cast<float (*)[33]>(&xs[0][0][0]);
    #pragma unroll
    for (int i = 0; i < 8; ++i)
        #pragma unroll
        for (int j = 0; j < 4; ++j)
            logits[wtok + r + 4 * i][c + 8 * j] = hadd2(acc[i][j]);
    __syncthreads();

    // epilogue: top-4 + softmax, one thread per token
    {
        const int t = tid;
        float bv0 = -1e30f, bv1 = -1e30f, bv2 = -1e30f, bv3 = -1e30f;
        int   bi0 = 0, bi1 = 0, bi2 = 0, bi3 = 0;
        #pragma unroll
        for (int e = 0; e < E_EXP; ++e) {
            float lv = logits[t][e] + bias_s[e];
            if (lv > bv3) {
                if (lv > bv0) {
                    bv3 = bv2; bi3 = bi2; bv2 = bv1; bi2 = bi1; bv1 = bv0; bi1 = bi0;
                    bv0 = lv;  bi0 = e;
                } else if (lv > bv1) {
                    bv3 = bv2; bi3 = bi2; bv2 = bv1; bi2 = bi1;
                    bv1 = lv;  bi1 = e;
                } else if (lv > bv2) {
                    bv3 = bv2; bi3 = bi2;
                    bv2 = lv;  bi2 = e;
                } else {
                    bv3 = lv;  bi3 = e;
                }
            }
        }
        float e0 = 1.0f;
        float e1 = expf(bv1 - bv0);
        float e2 = expf(bv2 - bv0);
        float e3 = expf(bv3 - bv0);
        float inv = 1.0f / (e0 + e1 + e2 + e3);

        const int gt = t0 + t;
        float* oi = out + (size_t)gt * TOPK;
        float* ow = out + (size_t)T_TOKENS * TOPK + (size_t)gt * TOPK;
        oi[0] = (float)bi0; oi[1] = (float)bi1; oi[2] = (float)bi2; oi[3] = (float)bi3;
        ow[0] = e0 * inv;   ow[1] = e1 * inv;   ow[2] = e2 * inv;   ow[3] = e3 * inv;
    }
}

extern "C" void kernel_launch(void* const* d_in, const int* in_sizes, int n_in,
                              void* d_out, int out_size)
{
    const float* x    = (const float*)d_in[0];  // [4,4096,2880] f32
    const float* w    = (const float*)d_in[1];  // [32,2880] f32
    const float* bias = (const float*)d_in[2];  // [32] f32
    float* out = (float*)d_out;

    dim3 grid(T_TOKENS / BM);   // 256 blocks
    dim3 block(NTHREADS);
    gate_kernel<<<grid, block>>>(x, w, bias, out);
}

// round 5
// speedup vs baseline: 1.7041x; 1.2995x over previous
#include <cuda_runtime.h>

#define T_TOKENS 16384
#define H_DIM    2880
#define E_EXP    32
#define TOPK     4
#define BM       64
#define BK       32
#define NTILES   (H_DIM / BK)   // 90
#define NTHREADS 128
#define XS       36             // smem row stride (144B): conflict-free for both a and b reads
#define NROWS    96             // 64 x-rows + 32 w-rows per tile buffer

typedef unsigned long long u64;

__device__ __forceinline__ u64 ffma2(u64 a, u64 b, u64 c) {
    u64 d;
    asm("fma.rn.f32x2 %0, %1, %2, %3;" : "=l"(d) : "l"(a), "l"(b), "l"(c));
    return d;
}
__device__ __forceinline__ unsigned smem_u32(const void* p) {
    return (unsigned)__cvta_generic_to_shared(p);
}
__device__ __forceinline__ void cp16(unsigned dst, const void* src) {
    asm volatile("cp.async.cg.shared.global [%0], [%1], 16;" :: "r"(dst), "l"(src));
}
__device__ __forceinline__ void cp_commit() {
    asm volatile("cp.async.commit_group;");
}
template <int N>
__device__ __forceinline__ void cp_wait() {
    asm volatile("cp.async.wait_group %0;" :: "n"(N));
}
__device__ __forceinline__ float hadd2(u64 v) {
    float lo, hi;
    asm("mov.b64 {%0, %1}, %2;" : "=f"(lo), "=f"(hi) : "l"(v));
    return lo + hi;
}

__global__ __launch_bounds__(NTHREADS, 2)
void gate_kernel(const float* __restrict__ x,
                 const float* __restrict__ w,
                 const float* __restrict__ bias,
                 float* __restrict__ out)
{
    // 4-stage pipeline; rows 0..63 = x tokens, rows 64..95 = w experts. K-major, f32x2 paired along K.
    __shared__ __align__(16) float buf[4][NROWS][XS];   // 4*96*36*4 = 55296 B
    __shared__ float logits[BM][E_EXP + 1];
    __shared__ float bias_s[E_EXP];

    const int tid = threadIdx.x;
    const int t0  = blockIdx.x * BM;

    if (tid < E_EXP) bias_s[tid] = bias[tid];

    const int lane = tid & 31;
    const int warp = tid >> 5;
    const int r    = lane >> 3;       // 0..3 -> tokens wtok + r + 4i (i<4)
    const int c    = lane & 7;        // 0..7 -> experts c + 8j (j<4)
    const int wtok = warp * 16;

    // prefetch mapping: chunk = tid + 128*i (i<6) -> row = (tid>>3) + 16*i, col16B = tid&7
    // i<4: x rows 0..63 ; i=4,5: w rows 0..31
    const int prow = tid >> 3;        // 0..15
    const int pcol = tid & 7;         // 0..7
    const float* xsrc = x + (size_t)(t0 + prow) * H_DIM + pcol * 4;
    const float* wsrc = w + (size_t)prow * H_DIM + pcol * 4;

    u64 acc[4][4];
    #pragma unroll
    for (int i = 0; i < 4; ++i)
        #pragma unroll
        for (int j = 0; j < 4; ++j) acc[i][j] = 0ull;

    auto prefetch = [&](int kt, int b) {
        const size_t k0 = (size_t)kt * BK;
        #pragma unroll
        for (int i = 0; i < 4; ++i)
            cp16(smem_u32(&buf[b][prow + 16 * i][pcol * 4]),
                 xsrc + k0 + (size_t)(16 * i) * H_DIM);
        #pragma unroll
        for (int i = 0; i < 2; ++i)
            cp16(smem_u32(&buf[b][64 + prow + 16 * i][pcol * 4]),
                 wsrc + k0 + (size_t)(16 * i) * H_DIM);
        cp_commit();
    };

    prefetch(0, 0);
    prefetch(1, 1);

    for (int kt = 0; kt < NTILES; ++kt) {
        if (kt + 2 < NTILES) {
            prefetch(kt + 2, (kt + 2) & 3);
            cp_wait<2>();
        } else if (kt + 1 < NTILES) {
            cp_wait<1>();
        } else {
            cp_wait<0>();
        }
        __syncthreads();   // single barrier per tile (safe: NBUF=4, depth=2)

        const float (*tb)[XS] = buf[kt & 3];

        #pragma unroll
        for (int kq = 0; kq < 8; ++kq) {
            ulonglong2 a[4], b[4];
            #pragma unroll
            for (int i = 0; i < 4; ++i)
                a[i] = *reinterpret_cast<const ulonglong2*>(&tb[wtok + r + 4 * i][kq * 4]);
            #pragma unroll
            for (int j = 0; j < 4; ++j)
                b[j] = *reinterpret_cast<const ulonglong2*>(&tb[64 + c + 8 * j][kq * 4]);

            #pragma unroll
            for (int i = 0; i < 4; ++i)
                #pragma unroll
                for (int j = 0; j < 4; ++j)
                    acc[i][j] = ffma2(a[i].x, b[j].x, acc[i][j]);
            #pragma unroll
            for (int i = 0; i < 4; ++i)
                #pragma unroll
                for (int j = 0; j < 4; ++j)
                    acc[i][j] = ffma2(a[i].y, b[j].y, acc[i][j]);
        }
    }

    #pragma unroll
    for (int i = 0; i < 4; ++i)
        #pragma unroll
        for (int j = 0; j < 4; ++j)
            logits[wtok + r + 4 * i][c + 8 * j] = hadd2(acc[i][j]);
    __syncthreads();

    // epilogue: top-4 + softmax, threads 0..63 handle one token each
    if (tid < BM) {
        const int t = tid;
        float bv0 = -1e30f, bv1 = -1e30f, bv2 = -1e30f, bv3 = -1e30f;
        int   bi0 = 0, bi1 = 0, bi2 = 0, bi3 = 0;
        #pragma unroll
        for (int e = 0; e < E_EXP; ++e) {
            float lv = logits[t][e] + bias_s[e];
            if (lv > bv3) {
                if (lv > bv0) {
                    bv3 = bv2; bi3 = bi2; bv2 = bv1; bi2 = bi1; bv1 = bv0; bi1 = bi0;
                    bv0 = lv;  bi0 = e;
                } else if (lv > bv1) {
                    bv3 = bv2; bi3 = bi2; bv2 = bv1; bi2 = bi1;
                    bv1 = lv;  bi1 = e;
                } else if (lv > bv2) {
                    bv3 = bv2; bi3 = bi2;
                    bv2 = lv;  bi2 = e;
                } else {
                    bv3 = lv;  bi3 = e;
                }
            }
        }
        float e0 = 1.0f;
        float e1 = expf(bv1 - bv0);
        float e2 = expf(bv2 - bv0);
        float e3 = expf(bv3 - bv0);
        float inv = 1.0f / (e0 + e1 + e2 + e3);

        const int gt = t0 + t;
        float* oi = out + (size_t)gt * TOPK;
        float* ow = out + (size_t)T_TOKENS * TOPK + (size_t)gt * TOPK;
        oi[0] = (float)bi0; oi[1] = (float)bi1; oi[2] = (float)bi2; oi[3] = (float)bi3;
        ow[0] = e0 * inv;   ow[1] = e1 * inv;   ow[2] = e2 * inv;   ow[3] = e3 * inv;
    }
}

extern "C" void kernel_launch(void* const* d_in, const int* in_sizes, int n_in,
                              void* d_out, int out_size)
{
    const float* x    = (const float*)d_in[0];  // [4,4096,2880] f32
    const float* w    = (const float*)d_in[1];  // [32,2880] f32
    const float* bias = (const float*)d_in[2];  // [32] f32
    float* out = (float*)d_out;

    dim3 grid(T_TOKENS / BM);   // 256 blocks x 4 warps = 1024 warps
    dim3 block(NTHREADS);
    gate_kernel<<<grid, block>>>(x, w, bias, out);
}